// round 10
// baseline (speedup 1.0000x reference)
#include <cuda_runtime.h>
#include <cuda_fp16.h>
#include <cstdint>

#define EPS 1e-5f

static constexpr int MAX_N = 50048;    // nodes (actual 50000)
static constexpr int MAX_E = 600064;   // edges (actual 600000)

// ---------------- scratch (device globals; no allocation allowed) ------------
__device__ float  g_deg[MAX_N];
__device__ int    g_cnt[MAX_N];
__device__ int    g_fill[MAX_N];
__device__ int    g_rowptr[MAX_N + 1];
__device__ int2   g_csr[MAX_E];        // (src, norm-bits)
__device__ float  g_dinv[MAX_N];
__device__ float  g_normself[MAX_N];
__device__ __align__(16) __half g_h2[MAX_N * 128];   // GEMM output, fp16 (gather source)
__device__ float4 g_out[MAX_N * 32];   // aggregation output (fp32)
__device__ float  g_stats[384];        // L1: [0:128)sum [128:256)sq ; L2: [256:320)sum [320:384)sq
__device__ unsigned long long g_scanstate[64];

// ---------------- PDL helpers --------------------------------------------------
__device__ __forceinline__ void pdl_wait() {
    asm volatile("griddepcontrol.wait;" ::: "memory");
}
__device__ __forceinline__ void pdl_trigger() {
    asm volatile("griddepcontrol.launch_dependents;" ::: "memory");
}

// ---------------- prep kernels (scalar: wavefront-bound, max occupancy) -------
__global__ void k_init(float* deg, int* cnt, float* stats, unsigned long long* state, int n) {
    int i = blockIdx.x * blockDim.x + threadIdx.x;
    if (i < n) { deg[i] = 1.0f; cnt[i] = 0; }   // self loop weight 1
    if (i < 384) stats[i] = 0.0f;               // zero ALL stats (both layers)
    if (i < 64) state[i] = 0ull;                // reset scan lookback state
}

__global__ void k_prep_edge(const int* __restrict__ dst, const float* __restrict__ w,
                            float* deg, int* cnt, int e) {
    int i = blockIdx.x * blockDim.x + threadIdx.x;
    if (i < e) {
        int d = dst[i];
        atomicAdd(deg + d, w[i]);
        atomicAdd(cnt + d, 1);
    }
}

// ---- fused single-pass scan (decoupled lookback) + dinv/normself -------------
__global__ void k_scan(const int* __restrict__ cnt, const float* __restrict__ deg,
                       float* dinv, float* normself, int* rowptr, int* fill,
                       volatile unsigned long long* state, int n, int e) {
    __shared__ int warpTot[8];
    __shared__ int blockOffSh;
    const int tid = threadIdx.x;
    const int lane = tid & 31;
    const int wid = tid >> 5;
    int tbase = blockIdx.x * 2048 + tid * 8;
    int v[8];
    int s = 0;
#pragma unroll
    for (int i = 0; i < 8; i++) {
        int idx = tbase + i;
        v[i] = (idx < n) ? cnt[idx] : 0;
        s += v[i];
        if (idx < n) {
            float d = deg[idx];
            float r = (d > 0.f) ? rsqrtf(d) : 0.f;
            dinv[idx] = r;
            normself[idx] = r * r;
        }
    }
    int inc = s;
#pragma unroll
    for (int o = 1; o < 32; o <<= 1) {
        int t = __shfl_up_sync(0xffffffffu, inc, o);
        if (lane >= o) inc += t;
    }
    if (lane == 31) warpTot[wid] = inc;
    __syncthreads();
    if (wid == 0) {
        int wv = (lane < 8) ? warpTot[lane] : 0;
        int winc = wv;
#pragma unroll
        for (int o = 1; o < 8; o <<= 1) {
            int t = __shfl_up_sync(0xffffffffu, winc, o);
            if (lane >= o) winc += t;
        }
        if (lane < 8) warpTot[lane] = winc - wv;   // exclusive warp offsets
        int blockTotal = __shfl_sync(0xffffffffu, winc, 7);
        if (lane == 0) {
            if (blockIdx.x == 0) {
                __threadfence();
                state[0] = ((unsigned long long)blockTotal << 2) | 2ull;  // prefix
                blockOffSh = 0;
                rowptr[n] = e;
            } else {
                __threadfence();
                state[blockIdx.x] = ((unsigned long long)blockTotal << 2) | 1ull;  // aggregate
                int excl = 0;
                int j = blockIdx.x - 1;
                while (true) {
                    unsigned long long vv;
                    do { vv = state[j]; } while ((vv & 3ull) == 0ull);
                    excl += (int)(vv >> 2);
                    if ((vv & 3ull) == 2ull) break;
                    j--;
                }
                __threadfence();
                state[blockIdx.x] = ((unsigned long long)(excl + blockTotal) << 2) | 2ull;
                blockOffSh = excl;
            }
        }
    }
    __syncthreads();
    int run = blockOffSh + warpTot[wid] + (inc - s);
#pragma unroll
    for (int i = 0; i < 8; i++) {
        int idx = tbase + i;
        if (idx < n) {
            rowptr[idx] = run;
            fill[idx] = run;
            run += v[i];
        }
    }
}

__global__ void k_place(const int* __restrict__ src, const int* __restrict__ dst,
                        const float* __restrict__ w, const float* __restrict__ dinv,
                        int* fill, int2* csr, int e) {
    int i = blockIdx.x * blockDim.x + threadIdx.x;
    if (i < e) {
        int s = src[i], d = dst[i];
        float nm = dinv[s] * w[i] * dinv[d];
        int pos = atomicAdd(fill + d, 1);
        csr[pos] = make_int2(s, __float_as_int(nm));
    }
}

// ---------------- tf32 helpers ------------------------------------------------
__device__ __forceinline__ uint32_t f2tf32(float f) {
    uint32_t r;
    asm("cvt.rna.tf32.f32 %0, %1;" : "=r"(r) : "f"(f));
    return r;
}

__device__ __forceinline__ void mma_tf32(float c[4], uint32_t a0, uint32_t a1,
                                         uint32_t a2, uint32_t a3,
                                         uint32_t b0, uint32_t b1) {
    asm volatile(
        "mma.sync.aligned.m16n8k8.row.col.f32.tf32.tf32.f32 "
        "{%0,%1,%2,%3}, {%4,%5,%6,%7}, {%8,%9}, {%0,%1,%2,%3};"
        : "+f"(c[0]), "+f"(c[1]), "+f"(c[2]), "+f"(c[3])
        : "r"(a0), "r"(a1), "r"(a2), "r"(a3), "r"(b0), "r"(b1));
}

// ---------------- tf32 tensor-core GEMM with inline BN(+ReLU), fp16 output ----
// PDL: B staging pre-wait; stats/A post-wait; trigger after A staged.
template <int K, int NOUT, bool BN>
__global__ void k_gemm_tc(const float* __restrict__ A, const float* __restrict__ B,
                          __half* __restrict__ C, int M,
                          const float* __restrict__ gamma, const float* __restrict__ beta,
                          const float* __restrict__ stats, float invN) {
    constexpr int BM = 128;
    constexpr int SA = K + 4;
    constexpr int SB = NOUT + 8;
    constexpr int NT = NOUT / 8;

    extern __shared__ uint32_t sm[];
    uint32_t* As = sm;              // [BM][SA]
    uint32_t* Bs = sm + BM * SA;    // [K][SB]
    __shared__ float sscale[K > 0 ? K : 1];
    __shared__ float sshift[K > 0 ? K : 1];

    const int tid = threadIdx.x;
    const int lane = tid & 31;
    const int warp = tid >> 5;
    const int rowBase = blockIdx.x * BM;

    // --- pre-wait prologue: stage B (weights are harness inputs) ---
    for (int l = tid; l < K * NOUT / 4; l += 256) {
        int r = l / (NOUT / 4);
        int c4 = l % (NOUT / 4);
        float4 v = *reinterpret_cast<const float4*>(B + (size_t)r * NOUT + c4 * 4);
        uint32_t* p = Bs + r * SB + c4 * 4;
        p[0] = f2tf32(v.x); p[1] = f2tf32(v.y); p[2] = f2tf32(v.z); p[3] = f2tf32(v.w);
    }

    pdl_wait();   // predecessor (agg) output now visible

    if (BN && tid < K) {
        float s = stats[tid];
        float q = stats[K + tid];
        float mean = s * invN;
        float var = q * invN - mean * mean;
        float sc = gamma[tid] * rsqrtf(var + EPS);
        sscale[tid] = sc;
        sshift[tid] = beta[tid] - mean * sc;
    }
    if (BN) __syncthreads();   // sscale/sshift visible before A staging

    for (int l = tid; l < BM * K / 4; l += 256) {
        int r = l / (K / 4);
        int c4 = l % (K / 4);
        int gr = rowBase + r;
        float4 v = make_float4(0.f, 0.f, 0.f, 0.f);
        if (gr < M) v = *reinterpret_cast<const float4*>(A + (size_t)gr * K + c4 * 4);
        if (BN) {
            v.x = fmaxf(fmaf(v.x, sscale[c4 * 4 + 0], sshift[c4 * 4 + 0]), 0.f);
            v.y = fmaxf(fmaf(v.y, sscale[c4 * 4 + 1], sshift[c4 * 4 + 1]), 0.f);
            v.z = fmaxf(fmaf(v.z, sscale[c4 * 4 + 2], sshift[c4 * 4 + 2]), 0.f);
            v.w = fmaxf(fmaf(v.w, sscale[c4 * 4 + 3], sshift[c4 * 4 + 3]), 0.f);
        }
        uint32_t* p = As + r * SA + c4 * 4;
        p[0] = f2tf32(v.x); p[1] = f2tf32(v.y); p[2] = f2tf32(v.z); p[3] = f2tf32(v.w);
    }
    __syncthreads();
    pdl_trigger();   // all global reads of A done; dependents may launch

    float acc[NT][4];
#pragma unroll
    for (int nt = 0; nt < NT; nt++) {
        acc[nt][0] = 0.f; acc[nt][1] = 0.f; acc[nt][2] = 0.f; acc[nt][3] = 0.f;
    }

    const int r0 = (warp << 4) + (lane >> 2);
    const int c0 = lane & 3;
    const int bcol = lane >> 2;

#pragma unroll 4
    for (int kk = 0; kk < K; kk += 8) {
        uint32_t a0 = As[r0 * SA + kk + c0];
        uint32_t a1 = As[(r0 + 8) * SA + kk + c0];
        uint32_t a2 = As[r0 * SA + kk + c0 + 4];
        uint32_t a3 = As[(r0 + 8) * SA + kk + c0 + 4];
#pragma unroll
        for (int nt = 0; nt < NT; nt++) {
            uint32_t b0 = Bs[(kk + c0) * SB + nt * 8 + bcol];
            uint32_t b1 = Bs[(kk + c0 + 4) * SB + nt * 8 + bcol];
            mma_tf32(acc[nt], a0, a1, a2, a3, b0, b1);
        }
    }

    int gr0 = rowBase + r0;
    int gr1 = gr0 + 8;
    if (gr0 < M) {
#pragma unroll
        for (int nt = 0; nt < NT; nt++) {
            __half2 hv = __floats2half2_rn(acc[nt][0], acc[nt][1]);
            *reinterpret_cast<__half2*>(C + (size_t)gr0 * NOUT + nt * 8 + c0 * 2) = hv;
        }
    }
    if (gr1 < M) {
#pragma unroll
        for (int nt = 0; nt < NT; nt++) {
            __half2 hv = __floats2half2_rn(acc[nt][2], acc[nt][3]);
            *reinterpret_cast<__half2*>(C + (size_t)gr1 * NOUT + nt * 8 + c0 * 2) = hv;
        }
    }
}

// ---------------- pull aggregation over fp16 h2 (8-edge unroll) ---------------
// Gathers are uint2 (8 bytes = 4 fp16 feats per lane): half the L2 traffic.
template <int FEAT, bool STATS>
__global__ void k_agg(const int* __restrict__ rowptr, const int2* __restrict__ csr,
                      const __half* __restrict__ h2, const float* __restrict__ bias,
                      const float* __restrict__ normself, float* __restrict__ out,
                      float* stats, int n) {
    constexpr int LPN = FEAT / 4;     // lanes per node
    constexpr int NPW = 32 / LPN;     // nodes per warp
    const int lane = threadIdx.x & 31;
    const int warpG = (blockIdx.x * blockDim.x + threadIdx.x) >> 5;
    const int nWarps = (gridDim.x * blockDim.x) >> 5;
    const int sub = lane / LPN;
    const int fc = lane % LPN;

    pdl_trigger();
    pdl_wait();

    float4 bb = *reinterpret_cast<const float4*>(bias + fc * 4);

    float s0 = 0.f, s1 = 0.f, s2 = 0.f, s3 = 0.f;
    float q0 = 0.f, q1 = 0.f, q2 = 0.f, q3 = 0.f;

    for (int node = warpG * NPW + sub; node < n; node += nWarps * NPW) {
        int beg = rowptr[node];
        int end = rowptr[node + 1];
        float ns = normself[node];
        // self row (fp16 -> fp32)
        uint2 hr = *reinterpret_cast<const uint2*>(h2 + (size_t)node * FEAT + fc * 4);
        float2 h01 = __half22float2(*reinterpret_cast<__half2*>(&hr.x));
        float2 h23 = __half22float2(*reinterpret_cast<__half2*>(&hr.y));
        float4 aA = make_float4(fmaf(ns, h01.x, bb.x), fmaf(ns, h01.y, bb.y),
                                fmaf(ns, h23.x, bb.z), fmaf(ns, h23.y, bb.w));
        float4 aB = make_float4(0.f, 0.f, 0.f, 0.f);
        float4 aC = make_float4(0.f, 0.f, 0.f, 0.f);
        float4 aD = make_float4(0.f, 0.f, 0.f, 0.f);
        int e = beg;
        for (; e + 7 < end; e += 8) {
            int2 m0 = csr[e],     m1 = csr[e + 1], m2 = csr[e + 2], m3 = csr[e + 3];
            int2 m4 = csr[e + 4], m5 = csr[e + 5], m6 = csr[e + 6], m7 = csr[e + 7];
            uint2 r0 = *reinterpret_cast<const uint2*>(h2 + (size_t)m0.x * FEAT + fc * 4);
            uint2 r1 = *reinterpret_cast<const uint2*>(h2 + (size_t)m1.x * FEAT + fc * 4);
            uint2 r2 = *reinterpret_cast<const uint2*>(h2 + (size_t)m2.x * FEAT + fc * 4);
            uint2 r3 = *reinterpret_cast<const uint2*>(h2 + (size_t)m3.x * FEAT + fc * 4);
            uint2 r4 = *reinterpret_cast<const uint2*>(h2 + (size_t)m4.x * FEAT + fc * 4);
            uint2 r5 = *reinterpret_cast<const uint2*>(h2 + (size_t)m5.x * FEAT + fc * 4);
            uint2 r6 = *reinterpret_cast<const uint2*>(h2 + (size_t)m6.x * FEAT + fc * 4);
            uint2 r7 = *reinterpret_cast<const uint2*>(h2 + (size_t)m7.x * FEAT + fc * 4);
            float n0 = __int_as_float(m0.y), n1 = __int_as_float(m1.y);
            float n2 = __int_as_float(m2.y), n3 = __int_as_float(m3.y);
            float n4 = __int_as_float(m4.y), n5 = __int_as_float(m5.y);
            float n6 = __int_as_float(m6.y), n7 = __int_as_float(m7.y);
            float2 a01, a23;
#define ACC_EDGE(rr, nn, T)                                                     \
            a01 = __half22float2(*reinterpret_cast<__half2*>(&rr.x));           \
            a23 = __half22float2(*reinterpret_cast<__half2*>(&rr.y));           \
            T.x = fmaf(nn, a01.x, T.x); T.y = fmaf(nn, a01.y, T.y);             \
            T.z = fmaf(nn, a23.x, T.z); T.w = fmaf(nn, a23.y, T.w);
            ACC_EDGE(r0, n0, aA) ACC_EDGE(r1, n1, aB)
            ACC_EDGE(r2, n2, aC) ACC_EDGE(r3, n3, aD)
            ACC_EDGE(r4, n4, aA) ACC_EDGE(r5, n5, aB)
            ACC_EDGE(r6, n6, aC) ACC_EDGE(r7, n7, aD)
        }
        for (; e < end; e++) {
            int2 m0 = csr[e];
            uint2 r0 = *reinterpret_cast<const uint2*>(h2 + (size_t)m0.x * FEAT + fc * 4);
            float n0 = __int_as_float(m0.y);
            float2 a01, a23;
            ACC_EDGE(r0, n0, aA)
        }
#undef ACC_EDGE
        float4 acc = make_float4((aA.x + aB.x) + (aC.x + aD.x),
                                 (aA.y + aB.y) + (aC.y + aD.y),
                                 (aA.z + aB.z) + (aC.z + aD.z),
                                 (aA.w + aB.w) + (aC.w + aD.w));
        *reinterpret_cast<float4*>(out + (size_t)node * FEAT + fc * 4) = acc;
        if (STATS) {
            s0 += acc.x; s1 += acc.y; s2 += acc.z; s3 += acc.w;
            q0 = fmaf(acc.x, acc.x, q0); q1 = fmaf(acc.y, acc.y, q1);
            q2 = fmaf(acc.z, acc.z, q2); q3 = fmaf(acc.w, acc.w, q3);
        }
    }

    if (STATS) {
#pragma unroll
        for (int off = 16; off >= LPN; off >>= 1) {
            s0 += __shfl_down_sync(0xffffffffu, s0, off);
            s1 += __shfl_down_sync(0xffffffffu, s1, off);
            s2 += __shfl_down_sync(0xffffffffu, s2, off);
            s3 += __shfl_down_sync(0xffffffffu, s3, off);
            q0 += __shfl_down_sync(0xffffffffu, q0, off);
            q1 += __shfl_down_sync(0xffffffffu, q1, off);
            q2 += __shfl_down_sync(0xffffffffu, q2, off);
            q3 += __shfl_down_sync(0xffffffffu, q3, off);
        }
        __shared__ float sh_s[8][FEAT];
        __shared__ float sh_q[8][FEAT];
        const int wid = threadIdx.x >> 5;
        if (lane < LPN) {
            sh_s[wid][fc * 4 + 0] = s0; sh_s[wid][fc * 4 + 1] = s1;
            sh_s[wid][fc * 4 + 2] = s2; sh_s[wid][fc * 4 + 3] = s3;
            sh_q[wid][fc * 4 + 0] = q0; sh_q[wid][fc * 4 + 1] = q1;
            sh_q[wid][fc * 4 + 2] = q2; sh_q[wid][fc * 4 + 3] = q3;
        }
        __syncthreads();
        int tid = threadIdx.x;
        if (tid < FEAT) {
            float a = 0.f, b = 0.f;
#pragma unroll
            for (int w = 0; w < 8; w++) { a += sh_s[w][tid]; b += sh_q[w][tid]; }
            atomicAdd(&stats[tid], a);
            atomicAdd(&stats[FEAT + tid], b);
        }
    }
}

// ---------------- host orchestration -----------------------------------------
static inline int cdiv(int a, int b) { return (a + b - 1) / b; }

extern "C" void kernel_launch(void* const* d_in, const int* in_sizes, int n_in,
                              void* d_out, int out_size) {
    const float* x      = (const float*)d_in[0];
    const int*   src    = (const int*)d_in[1];
    const int*   dst    = (const int*)d_in[2];
    const float* weight = (const float*)d_in[3];
    const float* W1 = (const float*)d_in[4];
    const float* b1 = (const float*)d_in[5];
    const float* ga1 = (const float*)d_in[6];
    const float* be1 = (const float*)d_in[7];
    const float* W2 = (const float*)d_in[8];
    const float* b2 = (const float*)d_in[9];
    const float* ga2 = (const float*)d_in[10];
    const float* be2 = (const float*)d_in[11];
    const float* W3 = (const float*)d_in[12];
    const float* b3 = (const float*)d_in[13];

    const int N = in_sizes[0] / 128;
    const int E = in_sizes[1];
    float* outp = (float*)d_out;

    void *p_deg, *p_cnt, *p_fill, *p_rowptr, *p_csr, *p_dinv, *p_ns, *p_h2, *p_out;
    void *p_state, *p_stats;
    cudaGetSymbolAddress(&p_deg, g_deg);
    cudaGetSymbolAddress(&p_cnt, g_cnt);
    cudaGetSymbolAddress(&p_fill, g_fill);
    cudaGetSymbolAddress(&p_rowptr, g_rowptr);
    cudaGetSymbolAddress(&p_csr, g_csr);
    cudaGetSymbolAddress(&p_dinv, g_dinv);
    cudaGetSymbolAddress(&p_ns, g_normself);
    cudaGetSymbolAddress(&p_h2, g_h2);
    cudaGetSymbolAddress(&p_out, g_out);
    cudaGetSymbolAddress(&p_state, g_scanstate);
    cudaGetSymbolAddress(&p_stats, g_stats);
    float* deg = (float*)p_deg;
    int* cnt = (int*)p_cnt;
    int* fill = (int*)p_fill;
    int* rowptr = (int*)p_rowptr;
    int2* csr = (int2*)p_csr;
    float* dinv = (float*)p_dinv;
    float* normself = (float*)p_ns;
    __half* h2 = (__half*)p_h2;
    float* agg = (float*)p_out;
    unsigned long long* scanstate = (unsigned long long*)p_state;
    float* stats1 = (float*)p_stats;        // layer1: 256 floats
    float* stats2 = (float*)p_stats + 256;  // layer2: 128 floats

    const float invN = 1.0f / (float)N;

    const int smem1 = (128 * (128 + 4) + 128 * (128 + 8)) * 4;
    const int smem2 = (128 * (128 + 4) + 128 * (64 + 8)) * 4;
    const int smem3 = (128 * (64 + 4) + 64 * (32 + 8)) * 4;
    cudaFuncSetAttribute(k_gemm_tc<128, 128, false>,
                         cudaFuncAttributeMaxDynamicSharedMemorySize, smem1);
    cudaFuncSetAttribute(k_gemm_tc<128, 64, true>,
                         cudaFuncAttributeMaxDynamicSharedMemorySize, smem2);
    cudaFuncSetAttribute(k_gemm_tc<64, 32, true>,
                         cudaFuncAttributeMaxDynamicSharedMemorySize, smem3);

    // side stream + fork/join events (host-side objects only)
    cudaStream_t s2;
    cudaEvent_t evFork, evJoin;
    cudaStreamCreateWithFlags(&s2, cudaStreamNonBlocking);
    cudaEventCreateWithFlags(&evFork, cudaEventDisableTiming);
    cudaEventCreateWithFlags(&evJoin, cudaEventDisableTiming);

    const int scanGrid = cdiv(N, 2048);   // 25 blocks for N=50000
    const int gemmGrid = cdiv(N, 128);
    const int aggGrid = 1184;             // 8 blocks/SM

    // ---- fork: CSR/normalization prep on s2, concurrent with Layer-1 GEMM ----
    cudaEventRecord(evFork, 0);
    cudaStreamWaitEvent(s2, evFork, 0);

    k_init<<<cdiv(N, 256), 256, 0, s2>>>(deg, cnt, stats1, scanstate, N);
    k_prep_edge<<<cdiv(E, 256), 256, 0, s2>>>(dst, weight, deg, cnt, E);
    k_scan<<<scanGrid, 256, 0, s2>>>(cnt, deg, dinv, normself, rowptr, fill, scanstate, N, E);
    k_place<<<cdiv(E, 256), 256, 0, s2>>>(src, dst, weight, dinv, fill, csr, E);
    cudaEventRecord(evJoin, s2);

    // Layer-1 GEMM on main stream (independent of prep)
    k_gemm_tc<128, 128, false><<<gemmGrid, 256, smem1>>>(x, W1, h2, N,
                                                         nullptr, nullptr, nullptr, invN);

    // ---- join: everything after needs both GEMM1 and the CSR ----
    cudaStreamWaitEvent(0, evJoin, 0);

    // agg1: plain launch (predecessor is an event-wait, not a kernel)
    k_agg<128, true><<<aggGrid, 256>>>(rowptr, csr, h2, b1, normself, agg, stats1, N);

    // PDL launch config for the rest of the chain
    cudaLaunchAttribute pdlAttr[1];
    pdlAttr[0].id = cudaLaunchAttributeProgrammaticStreamSerialization;
    pdlAttr[0].val.programmaticStreamSerializationAllowed = 1;

    {
        cudaLaunchConfig_t cfg{};
        cfg.gridDim = dim3(gemmGrid, 1, 1);
        cfg.blockDim = dim3(256, 1, 1);
        cfg.dynamicSmemBytes = smem2;
        cfg.stream = 0;
        cfg.attrs = pdlAttr;
        cfg.numAttrs = 1;
        cudaLaunchKernelEx(&cfg, k_gemm_tc<128, 64, true>, (const float*)agg, W2, h2, N,
                           ga1, be1, (const float*)stats1, invN);
    }
    {
        cudaLaunchConfig_t cfg{};
        cfg.gridDim = dim3(aggGrid, 1, 1);
        cfg.blockDim = dim3(256, 1, 1);
        cfg.dynamicSmemBytes = 0;
        cfg.stream = 0;
        cfg.attrs = pdlAttr;
        cfg.numAttrs = 1;
        cudaLaunchKernelEx(&cfg, k_agg<64, true>, (const int*)rowptr, (const int2*)csr,
                           (const __half*)h2, b2, (const float*)normself, agg, stats2, N);
    }
    {
        cudaLaunchConfig_t cfg{};
        cfg.gridDim = dim3(gemmGrid, 1, 1);
        cfg.blockDim = dim3(256, 1, 1);
        cfg.dynamicSmemBytes = smem3;
        cfg.stream = 0;
        cfg.attrs = pdlAttr;
        cfg.numAttrs = 1;
        cudaLaunchKernelEx(&cfg, k_gemm_tc<64, 32, true>, (const float*)agg, W3, h2, N,
                           ga2, be2, (const float*)stats2, invN);
    }
    {
        cudaLaunchConfig_t cfg{};
        cfg.gridDim = dim3(aggGrid, 1, 1);
        cfg.blockDim = dim3(256, 1, 1);
        cfg.dynamicSmemBytes = 0;
        cfg.stream = 0;
        cfg.attrs = pdlAttr;
        cfg.numAttrs = 1;
        cudaLaunchKernelEx(&cfg, k_agg<32, false>, (const int*)rowptr, (const int2*)csr,
                           (const __half*)h2, b3, (const float*)normself, outp,
                           (float*)nullptr, N);
    }
}

// round 11
// speedup vs baseline: 1.0267x; 1.0267x over previous
#include <cuda_runtime.h>
#include <cuda_bf16.h>
#include <cstdint>

#define EPS 1e-5f

static constexpr int MAX_N = 50048;    // nodes (actual 50000)
static constexpr int MAX_E = 600064;   // edges (actual 600000)

// ---------------- scratch (device globals; no allocation allowed) ------------
__device__ float  g_deg[MAX_N];
__device__ int    g_cnt[MAX_N];
__device__ int    g_fill[MAX_N];
__device__ int    g_rowptr[MAX_N + 1];
__device__ int2   g_csr[MAX_E];        // (src, w-bits)
__device__ float  g_dinv[MAX_N];
__device__ float4 g_h2[MAX_N * 32];    // GEMM output (dinv-scaled rows)
__device__ float4 g_out[MAX_N * 32];   // aggregation output
__device__ float  g_stats[384];        // L1: [0:128)sum [128:256)sq ; L2: [256:320)sum [320:384)sq
__device__ unsigned long long g_scanstate[64];

// ---------------- PDL helpers --------------------------------------------------
__device__ __forceinline__ void pdl_wait() {
    asm volatile("griddepcontrol.wait;" ::: "memory");
}
__device__ __forceinline__ void pdl_trigger() {
    asm volatile("griddepcontrol.launch_dependents;" ::: "memory");
}

// ---------------- prep kernels (scalar: wavefront-bound, max occupancy) -------
__global__ void k_init(float* deg, int* cnt, float* stats, unsigned long long* state, int n) {
    int i = blockIdx.x * blockDim.x + threadIdx.x;
    if (i < n) { deg[i] = 1.0f; cnt[i] = 0; }   // self loop weight 1
    if (i < 384) stats[i] = 0.0f;               // zero ALL stats (both layers)
    if (i < 64) state[i] = 0ull;                // reset scan lookback state
}

__global__ void k_prep_edge(const int* __restrict__ dst, const float* __restrict__ w,
                            float* deg, int* cnt, int e) {
    int i = blockIdx.x * blockDim.x + threadIdx.x;
    if (i < e) {
        int d = dst[i];
        atomicAdd(deg + d, w[i]);
        atomicAdd(cnt + d, 1);
    }
}

// ---- fused single-pass scan (decoupled lookback) + dinv -----------------------
__global__ void k_scan(const int* __restrict__ cnt, const float* __restrict__ deg,
                       float* dinv, int* rowptr, int* fill,
                       volatile unsigned long long* state, int n, int e) {
    __shared__ int warpTot[8];
    __shared__ int blockOffSh;
    const int tid = threadIdx.x;
    const int lane = tid & 31;
    const int wid = tid >> 5;
    int tbase = blockIdx.x * 2048 + tid * 8;
    int v[8];
    int s = 0;
#pragma unroll
    for (int i = 0; i < 8; i++) {
        int idx = tbase + i;
        v[i] = (idx < n) ? cnt[idx] : 0;
        s += v[i];
        if (idx < n) {
            float d = deg[idx];
            dinv[idx] = (d > 0.f) ? rsqrtf(d) : 0.f;
        }
    }
    int inc = s;
#pragma unroll
    for (int o = 1; o < 32; o <<= 1) {
        int t = __shfl_up_sync(0xffffffffu, inc, o);
        if (lane >= o) inc += t;
    }
    if (lane == 31) warpTot[wid] = inc;
    __syncthreads();
    if (wid == 0) {
        int wv = (lane < 8) ? warpTot[lane] : 0;
        int winc = wv;
#pragma unroll
        for (int o = 1; o < 8; o <<= 1) {
            int t = __shfl_up_sync(0xffffffffu, winc, o);
            if (lane >= o) winc += t;
        }
        if (lane < 8) warpTot[lane] = winc - wv;   // exclusive warp offsets
        int blockTotal = __shfl_sync(0xffffffffu, winc, 7);
        if (lane == 0) {
            if (blockIdx.x == 0) {
                __threadfence();
                state[0] = ((unsigned long long)blockTotal << 2) | 2ull;  // prefix
                blockOffSh = 0;
                rowptr[n] = e;
            } else {
                __threadfence();
                state[blockIdx.x] = ((unsigned long long)blockTotal << 2) | 1ull;  // aggregate
                int excl = 0;
                int j = blockIdx.x - 1;
                while (true) {
                    unsigned long long vv;
                    do { vv = state[j]; } while ((vv & 3ull) == 0ull);
                    excl += (int)(vv >> 2);
                    if ((vv & 3ull) == 2ull) break;
                    j--;
                }
                __threadfence();
                state[blockIdx.x] = ((unsigned long long)(excl + blockTotal) << 2) | 2ull;
                blockOffSh = excl;
            }
        }
    }
    __syncthreads();
    int run = blockOffSh + warpTot[wid] + (inc - s);
#pragma unroll
    for (int i = 0; i < 8; i++) {
        int idx = tbase + i;
        if (idx < n) {
            rowptr[idx] = run;
            fill[idx] = run;
            run += v[i];
        }
    }
}

// place: NO dinv gathers — csr stores (src, raw edge weight)
__global__ void k_place(const int* __restrict__ src, const int* __restrict__ dst,
                        const float* __restrict__ w,
                        int* fill, int2* csr, int e) {
    int i = blockIdx.x * blockDim.x + threadIdx.x;
    if (i < e) {
        int d = dst[i];
        int pos = atomicAdd(fill + d, 1);
        csr[pos] = make_int2(src[i], __float_as_int(w[i]));
    }
}

// ---------------- tf32 helpers ------------------------------------------------
__device__ __forceinline__ uint32_t f2tf32(float f) {
    uint32_t r;
    asm("cvt.rna.tf32.f32 %0, %1;" : "=r"(r) : "f"(f));
    return r;
}

__device__ __forceinline__ void mma_tf32(float c[4], uint32_t a0, uint32_t a1,
                                         uint32_t a2, uint32_t a3,
                                         uint32_t b0, uint32_t b1) {
    asm volatile(
        "mma.sync.aligned.m16n8k8.row.col.f32.tf32.tf32.f32 "
        "{%0,%1,%2,%3}, {%4,%5,%6,%7}, {%8,%9}, {%0,%1,%2,%3};"
        : "+f"(c[0]), "+f"(c[1]), "+f"(c[2]), "+f"(c[3])
        : "r"(a0), "r"(a1), "r"(a2), "r"(a3), "r"(b0), "r"(b1));
}

// ---------------- tf32 GEMM with inline BN(+ReLU) on A; dinv-scaled output ----
// C[row] = dinv[row] * (BN(A)[row] @ B)   (h-hat rows for the pull aggregation)
template <int K, int NOUT, bool BN>
__global__ void k_gemm_tc(const float* __restrict__ A, const float* __restrict__ B,
                          float* __restrict__ C, int M,
                          const float* __restrict__ gamma, const float* __restrict__ beta,
                          const float* __restrict__ stats, float invN,
                          const float* __restrict__ dinv) {
    constexpr int BM = 128;
    constexpr int SA = K + 4;
    constexpr int SB = NOUT + 8;
    constexpr int NT = NOUT / 8;

    extern __shared__ uint32_t sm[];
    uint32_t* As = sm;              // [BM][SA]
    uint32_t* Bs = sm + BM * SA;    // [K][SB]
    __shared__ float sscale[K > 0 ? K : 1];
    __shared__ float sshift[K > 0 ? K : 1];

    const int tid = threadIdx.x;
    const int lane = tid & 31;
    const int warp = tid >> 5;
    const int rowBase = blockIdx.x * BM;

    // --- pre-wait prologue: stage B (weights are harness inputs) ---
    for (int l = tid; l < K * NOUT / 4; l += 256) {
        int r = l / (NOUT / 4);
        int c4 = l % (NOUT / 4);
        float4 v = *reinterpret_cast<const float4*>(B + (size_t)r * NOUT + c4 * 4);
        uint32_t* p = Bs + r * SB + c4 * 4;
        p[0] = f2tf32(v.x); p[1] = f2tf32(v.y); p[2] = f2tf32(v.z); p[3] = f2tf32(v.w);
    }

    pdl_wait();   // predecessor (agg) output now visible

    if (BN && tid < K) {
        float s = stats[tid];
        float q = stats[K + tid];
        float mean = s * invN;
        float var = q * invN - mean * mean;
        float sc = gamma[tid] * rsqrtf(var + EPS);
        sscale[tid] = sc;
        sshift[tid] = beta[tid] - mean * sc;
    }
    if (BN) __syncthreads();   // sscale/sshift visible before A staging

    for (int l = tid; l < BM * K / 4; l += 256) {
        int r = l / (K / 4);
        int c4 = l % (K / 4);
        int gr = rowBase + r;
        float4 v = make_float4(0.f, 0.f, 0.f, 0.f);
        if (gr < M) v = *reinterpret_cast<const float4*>(A + (size_t)gr * K + c4 * 4);
        if (BN) {
            v.x = fmaxf(fmaf(v.x, sscale[c4 * 4 + 0], sshift[c4 * 4 + 0]), 0.f);
            v.y = fmaxf(fmaf(v.y, sscale[c4 * 4 + 1], sshift[c4 * 4 + 1]), 0.f);
            v.z = fmaxf(fmaf(v.z, sscale[c4 * 4 + 2], sshift[c4 * 4 + 2]), 0.f);
            v.w = fmaxf(fmaf(v.w, sscale[c4 * 4 + 3], sshift[c4 * 4 + 3]), 0.f);
        }
        uint32_t* p = As + r * SA + c4 * 4;
        p[0] = f2tf32(v.x); p[1] = f2tf32(v.y); p[2] = f2tf32(v.z); p[3] = f2tf32(v.w);
    }
    __syncthreads();
    pdl_trigger();   // all global reads of A done; dependents may launch

    float acc[NT][4];
#pragma unroll
    for (int nt = 0; nt < NT; nt++) {
        acc[nt][0] = 0.f; acc[nt][1] = 0.f; acc[nt][2] = 0.f; acc[nt][3] = 0.f;
    }

    const int r0 = (warp << 4) + (lane >> 2);
    const int c0 = lane & 3;
    const int bcol = lane >> 2;

#pragma unroll 4
    for (int kk = 0; kk < K; kk += 8) {
        uint32_t a0 = As[r0 * SA + kk + c0];
        uint32_t a1 = As[(r0 + 8) * SA + kk + c0];
        uint32_t a2 = As[r0 * SA + kk + c0 + 4];
        uint32_t a3 = As[(r0 + 8) * SA + kk + c0 + 4];
#pragma unroll
        for (int nt = 0; nt < NT; nt++) {
            uint32_t b0 = Bs[(kk + c0) * SB + nt * 8 + bcol];
            uint32_t b1 = Bs[(kk + c0 + 4) * SB + nt * 8 + bcol];
            mma_tf32(acc[nt], a0, a1, a2, a3, b0, b1);
        }
    }

    int gr0 = rowBase + r0;
    int gr1 = gr0 + 8;
    if (gr0 < M) {
        float dv = dinv[gr0];
#pragma unroll
        for (int nt = 0; nt < NT; nt++)
            *reinterpret_cast<float2*>(C + (size_t)gr0 * NOUT + nt * 8 + c0 * 2) =
                make_float2(acc[nt][0] * dv, acc[nt][1] * dv);
    }
    if (gr1 < M) {
        float dv = dinv[gr1];
#pragma unroll
        for (int nt = 0; nt < NT; nt++)
            *reinterpret_cast<float2*>(C + (size_t)gr1 * NOUT + nt * 8 + c0 * 2) =
                make_float2(acc[nt][2] * dv, acc[nt][3] * dv);
    }
}

// ---------------- pull aggregation (8-edge unroll, 4 accumulator sets) --------
// h2 rows are dinv-scaled: out[d] = dinv[d]*(sum_e w_e*h2[src] + h2[d]) + b
template <int FEAT, bool STATS>
__global__ void k_agg(const int* __restrict__ rowptr, const int2* __restrict__ csr,
                      const float* __restrict__ h2, const float* __restrict__ bias,
                      const float* __restrict__ dinv, float* __restrict__ out,
                      float* stats, int n) {
    constexpr int LPN = FEAT / 4;     // lanes per node
    constexpr int NPW = 32 / LPN;     // nodes per warp
    const int lane = threadIdx.x & 31;
    const int warpG = (blockIdx.x * blockDim.x + threadIdx.x) >> 5;
    const int nWarps = (gridDim.x * blockDim.x) >> 5;
    const int sub = lane / LPN;
    const int fc = lane % LPN;

    pdl_trigger();
    pdl_wait();

    float4 bb = *reinterpret_cast<const float4*>(bias + fc * 4);

    float s0 = 0.f, s1 = 0.f, s2 = 0.f, s3 = 0.f;
    float q0 = 0.f, q1 = 0.f, q2 = 0.f, q3 = 0.f;

    for (int node = warpG * NPW + sub; node < n; node += nWarps * NPW) {
        int beg = rowptr[node];
        int end = rowptr[node + 1];
        float dn = dinv[node];
        float4 aA = *reinterpret_cast<const float4*>(h2 + (size_t)node * FEAT + fc * 4);
        float4 aB = make_float4(0.f, 0.f, 0.f, 0.f);
        float4 aC = make_float4(0.f, 0.f, 0.f, 0.f);
        float4 aD = make_float4(0.f, 0.f, 0.f, 0.f);
        int e = beg;
        for (; e + 7 < end; e += 8) {
            int2 m0 = csr[e],     m1 = csr[e + 1], m2 = csr[e + 2], m3 = csr[e + 3];
            int2 m4 = csr[e + 4], m5 = csr[e + 5], m6 = csr[e + 6], m7 = csr[e + 7];
            float4 v0 = *reinterpret_cast<const float4*>(h2 + (size_t)m0.x * FEAT + fc * 4);
            float4 v1 = *reinterpret_cast<const float4*>(h2 + (size_t)m1.x * FEAT + fc * 4);
            float4 v2 = *reinterpret_cast<const float4*>(h2 + (size_t)m2.x * FEAT + fc * 4);
            float4 v3 = *reinterpret_cast<const float4*>(h2 + (size_t)m3.x * FEAT + fc * 4);
            float4 v4 = *reinterpret_cast<const float4*>(h2 + (size_t)m4.x * FEAT + fc * 4);
            float4 v5 = *reinterpret_cast<const float4*>(h2 + (size_t)m5.x * FEAT + fc * 4);
            float4 v6 = *reinterpret_cast<const float4*>(h2 + (size_t)m6.x * FEAT + fc * 4);
            float4 v7 = *reinterpret_cast<const float4*>(h2 + (size_t)m7.x * FEAT + fc * 4);
            float n0 = __int_as_float(m0.y), n1 = __int_as_float(m1.y);
            float n2 = __int_as_float(m2.y), n3 = __int_as_float(m3.y);
            float n4 = __int_as_float(m4.y), n5 = __int_as_float(m5.y);
            float n6 = __int_as_float(m6.y), n7 = __int_as_float(m7.y);
            aA.x = fmaf(n0, v0.x, aA.x); aB.x = fmaf(n1, v1.x, aB.x);
            aC.x = fmaf(n2, v2.x, aC.x); aD.x = fmaf(n3, v3.x, aD.x);
            aA.y = fmaf(n0, v0.y, aA.y); aB.y = fmaf(n1, v1.y, aB.y);
            aC.y = fmaf(n2, v2.y, aC.y); aD.y = fmaf(n3, v3.y, aD.y);
            aA.z = fmaf(n0, v0.z, aA.z); aB.z = fmaf(n1, v1.z, aB.z);
            aC.z = fmaf(n2, v2.z, aC.z); aD.z = fmaf(n3, v3.z, aD.z);
            aA.w = fmaf(n0, v0.w, aA.w); aB.w = fmaf(n1, v1.w, aB.w);
            aC.w = fmaf(n2, v2.w, aC.w); aD.w = fmaf(n3, v3.w, aD.w);
            aA.x = fmaf(n4, v4.x, aA.x); aB.x = fmaf(n5, v5.x, aB.x);
            aC.x = fmaf(n6, v6.x, aC.x); aD.x = fmaf(n7, v7.x, aD.x);
            aA.y = fmaf(n4, v4.y, aA.y); aB.y = fmaf(n5, v5.y, aB.y);
            aC.y = fmaf(n6, v6.y, aC.y); aD.y = fmaf(n7, v7.y, aD.y);
            aA.z = fmaf(n4, v4.z, aA.z); aB.z = fmaf(n5, v5.z, aB.z);
            aC.z = fmaf(n6, v6.z, aC.z); aD.z = fmaf(n7, v7.z, aD.z);
            aA.w = fmaf(n4, v4.w, aA.w); aB.w = fmaf(n5, v5.w, aB.w);
            aC.w = fmaf(n6, v6.w, aC.w); aD.w = fmaf(n7, v7.w, aD.w);
        }
        for (; e + 1 < end; e += 2) {
            int2 m0 = csr[e], m1 = csr[e + 1];
            float4 v0 = *reinterpret_cast<const float4*>(h2 + (size_t)m0.x * FEAT + fc * 4);
            float4 v1 = *reinterpret_cast<const float4*>(h2 + (size_t)m1.x * FEAT + fc * 4);
            float n0 = __int_as_float(m0.y), n1 = __int_as_float(m1.y);
            aA.x = fmaf(n0, v0.x, aA.x); aB.x = fmaf(n1, v1.x, aB.x);
            aA.y = fmaf(n0, v0.y, aA.y); aB.y = fmaf(n1, v1.y, aB.y);
            aA.z = fmaf(n0, v0.z, aA.z); aB.z = fmaf(n1, v1.z, aB.z);
            aA.w = fmaf(n0, v0.w, aA.w); aB.w = fmaf(n1, v1.w, aB.w);
        }
        if (e < end) {
            int2 m0 = csr[e];
            float4 v0 = *reinterpret_cast<const float4*>(h2 + (size_t)m0.x * FEAT + fc * 4);
            float n0 = __int_as_float(m0.y);
            aA.x = fmaf(n0, v0.x, aA.x);
            aA.y = fmaf(n0, v0.y, aA.y);
            aA.z = fmaf(n0, v0.z, aA.z);
            aA.w = fmaf(n0, v0.w, aA.w);
        }
        float4 acc;
        acc.x = fmaf((aA.x + aB.x) + (aC.x + aD.x), dn, bb.x);
        acc.y = fmaf((aA.y + aB.y) + (aC.y + aD.y), dn, bb.y);
        acc.z = fmaf((aA.z + aB.z) + (aC.z + aD.z), dn, bb.z);
        acc.w = fmaf((aA.w + aB.w) + (aC.w + aD.w), dn, bb.w);
        *reinterpret_cast<float4*>(out + (size_t)node * FEAT + fc * 4) = acc;
        if (STATS) {
            s0 += acc.x; s1 += acc.y; s2 += acc.z; s3 += acc.w;
            q0 = fmaf(acc.x, acc.x, q0); q1 = fmaf(acc.y, acc.y, q1);
            q2 = fmaf(acc.z, acc.z, q2); q3 = fmaf(acc.w, acc.w, q3);
        }
    }

    if (STATS) {
#pragma unroll
        for (int off = 16; off >= LPN; off >>= 1) {
            s0 += __shfl_down_sync(0xffffffffu, s0, off);
            s1 += __shfl_down_sync(0xffffffffu, s1, off);
            s2 += __shfl_down_sync(0xffffffffu, s2, off);
            s3 += __shfl_down_sync(0xffffffffu, s3, off);
            q0 += __shfl_down_sync(0xffffffffu, q0, off);
            q1 += __shfl_down_sync(0xffffffffu, q1, off);
            q2 += __shfl_down_sync(0xffffffffu, q2, off);
            q3 += __shfl_down_sync(0xffffffffu, q3, off);
        }
        __shared__ float sh_s[8][FEAT];
        __shared__ float sh_q[8][FEAT];
        const int wid = threadIdx.x >> 5;
        if (lane < LPN) {
            sh_s[wid][fc * 4 + 0] = s0; sh_s[wid][fc * 4 + 1] = s1;
            sh_s[wid][fc * 4 + 2] = s2; sh_s[wid][fc * 4 + 3] = s3;
            sh_q[wid][fc * 4 + 0] = q0; sh_q[wid][fc * 4 + 1] = q1;
            sh_q[wid][fc * 4 + 2] = q2; sh_q[wid][fc * 4 + 3] = q3;
        }
        __syncthreads();
        int tid = threadIdx.x;
        if (tid < FEAT) {
            float a = 0.f, b = 0.f;
#pragma unroll
            for (int w = 0; w < 8; w++) { a += sh_s[w][tid]; b += sh_q[w][tid]; }
            atomicAdd(&stats[tid], a);
            atomicAdd(&stats[FEAT + tid], b);
        }
    }
}

// ---------------- host orchestration -----------------------------------------
static inline int cdiv(int a, int b) { return (a + b - 1) / b; }

extern "C" void kernel_launch(void* const* d_in, const int* in_sizes, int n_in,
                              void* d_out, int out_size) {
    const float* x      = (const float*)d_in[0];
    const int*   src    = (const int*)d_in[1];
    const int*   dst    = (const int*)d_in[2];
    const float* weight = (const float*)d_in[3];
    const float* W1 = (const float*)d_in[4];
    const float* b1 = (const float*)d_in[5];
    const float* ga1 = (const float*)d_in[6];
    const float* be1 = (const float*)d_in[7];
    const float* W2 = (const float*)d_in[8];
    const float* b2 = (const float*)d_in[9];
    const float* ga2 = (const float*)d_in[10];
    const float* be2 = (const float*)d_in[11];
    const float* W3 = (const float*)d_in[12];
    const float* b3 = (const float*)d_in[13];

    const int N = in_sizes[0] / 128;
    const int E = in_sizes[1];
    float* outp = (float*)d_out;

    void *p_deg, *p_cnt, *p_fill, *p_rowptr, *p_csr, *p_dinv, *p_h2, *p_out;
    void *p_state, *p_stats;
    cudaGetSymbolAddress(&p_deg, g_deg);
    cudaGetSymbolAddress(&p_cnt, g_cnt);
    cudaGetSymbolAddress(&p_fill, g_fill);
    cudaGetSymbolAddress(&p_rowptr, g_rowptr);
    cudaGetSymbolAddress(&p_csr, g_csr);
    cudaGetSymbolAddress(&p_dinv, g_dinv);
    cudaGetSymbolAddress(&p_h2, g_h2);
    cudaGetSymbolAddress(&p_out, g_out);
    cudaGetSymbolAddress(&p_state, g_scanstate);
    cudaGetSymbolAddress(&p_stats, g_stats);
    float* deg = (float*)p_deg;
    int* cnt = (int*)p_cnt;
    int* fill = (int*)p_fill;
    int* rowptr = (int*)p_rowptr;
    int2* csr = (int2*)p_csr;
    float* dinv = (float*)p_dinv;
    float* h2 = (float*)p_h2;
    float* agg = (float*)p_out;
    unsigned long long* scanstate = (unsigned long long*)p_state;
    float* stats1 = (float*)p_stats;        // layer1: 256 floats
    float* stats2 = (float*)p_stats + 256;  // layer2: 128 floats

    const float invN = 1.0f / (float)N;

    const int smem1 = (128 * (128 + 4) + 128 * (128 + 8)) * 4;
    const int smem2 = (128 * (128 + 4) + 128 * (64 + 8)) * 4;
    const int smem3 = (128 * (64 + 4) + 64 * (32 + 8)) * 4;
    cudaFuncSetAttribute(k_gemm_tc<128, 128, false>,
                         cudaFuncAttributeMaxDynamicSharedMemorySize, smem1);
    cudaFuncSetAttribute(k_gemm_tc<128, 64, true>,
                         cudaFuncAttributeMaxDynamicSharedMemorySize, smem2);
    cudaFuncSetAttribute(k_gemm_tc<64, 32, true>,
                         cudaFuncAttributeMaxDynamicSharedMemorySize, smem3);

    // side stream + fork/join events (host-side objects only)
    cudaStream_t s2;
    cudaEvent_t evFork, evScan, evJoin;
    cudaStreamCreateWithFlags(&s2, cudaStreamNonBlocking);
    cudaEventCreateWithFlags(&evFork, cudaEventDisableTiming);
    cudaEventCreateWithFlags(&evScan, cudaEventDisableTiming);
    cudaEventCreateWithFlags(&evJoin, cudaEventDisableTiming);

    const int scanGrid = cdiv(N, 2048);   // 25 blocks for N=50000
    const int gemmGrid = cdiv(N, 128);
    const int aggGrid = 1184;             // 8 blocks/SM

    // ---- fork: CSR/normalization prep on s2 ----
    cudaEventRecord(evFork, 0);
    cudaStreamWaitEvent(s2, evFork, 0);

    k_init<<<cdiv(N, 256), 256, 0, s2>>>(deg, cnt, stats1, scanstate, N);
    k_prep_edge<<<cdiv(E, 256), 256, 0, s2>>>(dst, weight, deg, cnt, E);
    k_scan<<<scanGrid, 256, 0, s2>>>(cnt, deg, dinv, rowptr, fill, scanstate, N, E);
    cudaEventRecord(evScan, s2);          // dinv + rowptr ready
    k_place<<<cdiv(E, 256), 256, 0, s2>>>(src, dst, weight, fill, csr, E);
    cudaEventRecord(evJoin, s2);          // csr ready

    // Layer-1 GEMM on main stream: needs dinv (epilogue) -> wait for scan only;
    // runs concurrently with k_place.
    cudaStreamWaitEvent(0, evScan, 0);
    k_gemm_tc<128, 128, false><<<gemmGrid, 256, smem1>>>(x, W1, h2, N,
                                                         nullptr, nullptr, nullptr, invN,
                                                         dinv);

    // ---- join: aggregation needs the CSR ----
    cudaStreamWaitEvent(0, evJoin, 0);

    // agg1: plain launch (predecessor is an event-wait, not a kernel)
    k_agg<128, true><<<aggGrid, 256>>>(rowptr, csr, h2, b1, dinv, agg, stats1, N);

    // PDL launch config for the rest of the chain
    cudaLaunchAttribute pdlAttr[1];
    pdlAttr[0].id = cudaLaunchAttributeProgrammaticStreamSerialization;
    pdlAttr[0].val.programmaticStreamSerializationAllowed = 1;

    {
        cudaLaunchConfig_t cfg{};
        cfg.gridDim = dim3(gemmGrid, 1, 1);
        cfg.blockDim = dim3(256, 1, 1);
        cfg.dynamicSmemBytes = smem2;
        cfg.stream = 0;
        cfg.attrs = pdlAttr;
        cfg.numAttrs = 1;
        cudaLaunchKernelEx(&cfg, k_gemm_tc<128, 64, true>, (const float*)agg, W2, h2, N,
                           ga1, be1, (const float*)stats1, invN, (const float*)dinv);
    }
    {
        cudaLaunchConfig_t cfg{};
        cfg.gridDim = dim3(aggGrid, 1, 1);
        cfg.blockDim = dim3(256, 1, 1);
        cfg.dynamicSmemBytes = 0;
        cfg.stream = 0;
        cfg.attrs = pdlAttr;
        cfg.numAttrs = 1;
        cudaLaunchKernelEx(&cfg, k_agg<64, true>, (const int*)rowptr, (const int2*)csr,
                           (const float*)h2, b2, (const float*)dinv, agg, stats2, N);
    }
    {
        cudaLaunchConfig_t cfg{};
        cfg.gridDim = dim3(gemmGrid, 1, 1);
        cfg.blockDim = dim3(256, 1, 1);
        cfg.dynamicSmemBytes = smem3;
        cfg.stream = 0;
        cfg.attrs = pdlAttr;
        cfg.numAttrs = 1;
        cudaLaunchKernelEx(&cfg, k_gemm_tc<64, 32, true>, (const float*)agg, W3, h2, N,
                           ga2, be2, (const float*)stats2, invN, (const float*)dinv);
    }
    {
        cudaLaunchConfig_t cfg{};
        cfg.gridDim = dim3(aggGrid, 1, 1);
        cfg.blockDim = dim3(256, 1, 1);
        cfg.dynamicSmemBytes = 0;
        cfg.stream = 0;
        cfg.attrs = pdlAttr;
        cfg.numAttrs = 1;
        cudaLaunchKernelEx(&cfg, k_agg<32, false>, (const int*)rowptr, (const int2*)csr,
                           (const float*)h2, b3, (const float*)dinv, outp,
                           (float*)nullptr, N);
    }
}

// round 12
// speedup vs baseline: 1.0391x; 1.0121x over previous
#include <cuda_runtime.h>
#include <cuda_bf16.h>
#include <cstdint>

#define EPS 1e-5f

static constexpr int MAX_N = 50048;    // nodes (actual 50000)
static constexpr int MAX_E = 600064;   // edges (actual 600000)

// ---------------- scratch (device globals; no allocation allowed) ------------
__device__ float  g_deg[MAX_N];
__device__ int    g_cnt[MAX_N];
__device__ int    g_fill[MAX_N];
__device__ int    g_rowptr[MAX_N + 1];
__device__ int2   g_csr[MAX_E];        // (src, norm-bits)
__device__ float  g_dinv[MAX_N];
__device__ float  g_normself[MAX_N];
__device__ float4 g_h2[MAX_N * 32];    // GEMM output (up to 128 f/node)
__device__ float4 g_out[MAX_N * 32];   // aggregation output
__device__ float  g_stats[384];        // L1: [0:128)sum [128:256)sq ; L2: [256:320)sum [320:384)sq
__device__ unsigned long long g_scanstate[64];

// ---------------- PDL helpers --------------------------------------------------
__device__ __forceinline__ void pdl_wait() {
    asm volatile("griddepcontrol.wait;" ::: "memory");
}
__device__ __forceinline__ void pdl_trigger() {
    asm volatile("griddepcontrol.launch_dependents;" ::: "memory");
}

// ---------------- prep kernels (scalar: wavefront-bound, max occupancy) -------
__global__ void k_init(float* deg, int* cnt, float* stats, unsigned long long* state, int n) {
    int i = blockIdx.x * blockDim.x + threadIdx.x;
    if (i < n) { deg[i] = 1.0f; cnt[i] = 0; }   // self loop weight 1
    if (i < 384) stats[i] = 0.0f;               // zero ALL stats (both layers)
    if (i < 64) state[i] = 0ull;                // reset scan lookback state
}

__global__ void k_prep_edge(const int* __restrict__ dst, const float* __restrict__ w,
                            float* deg, int* cnt, int e) {
    pdl_wait();   // k_init's zeroing must be visible
    int i = blockIdx.x * blockDim.x + threadIdx.x;
    if (i < e) {
        int d = dst[i];
        atomicAdd(deg + d, w[i]);
        atomicAdd(cnt + d, 1);
    }
}

// ---- fused single-pass scan (decoupled lookback) + dinv/normself -------------
__global__ void k_scan(const int* __restrict__ cnt, const float* __restrict__ deg,
                       float* dinv, float* normself, int* rowptr, int* fill,
                       volatile unsigned long long* state, int n, int e) {
    pdl_wait();   // k_prep_edge's deg/cnt must be complete
    __shared__ int warpTot[8];
    __shared__ int blockOffSh;
    const int tid = threadIdx.x;
    const int lane = tid & 31;
    const int wid = tid >> 5;
    int tbase = blockIdx.x * 2048 + tid * 8;
    int v[8];
    int s = 0;
#pragma unroll
    for (int i = 0; i < 8; i++) {
        int idx = tbase + i;
        v[i] = (idx < n) ? cnt[idx] : 0;
        s += v[i];
        if (idx < n) {
            float d = deg[idx];
            float r = (d > 0.f) ? rsqrtf(d) : 0.f;
            dinv[idx] = r;
            normself[idx] = r * r;
        }
    }
    int inc = s;
#pragma unroll
    for (int o = 1; o < 32; o <<= 1) {
        int t = __shfl_up_sync(0xffffffffu, inc, o);
        if (lane >= o) inc += t;
    }
    if (lane == 31) warpTot[wid] = inc;
    __syncthreads();
    if (wid == 0) {
        int wv = (lane < 8) ? warpTot[lane] : 0;
        int winc = wv;
#pragma unroll
        for (int o = 1; o < 8; o <<= 1) {
            int t = __shfl_up_sync(0xffffffffu, winc, o);
            if (lane >= o) winc += t;
        }
        if (lane < 8) warpTot[lane] = winc - wv;   // exclusive warp offsets
        int blockTotal = __shfl_sync(0xffffffffu, winc, 7);
        if (lane == 0) {
            if (blockIdx.x == 0) {
                __threadfence();
                state[0] = ((unsigned long long)blockTotal << 2) | 2ull;  // prefix
                blockOffSh = 0;
                rowptr[n] = e;
            } else {
                __threadfence();
                state[blockIdx.x] = ((unsigned long long)blockTotal << 2) | 1ull;  // aggregate
                int excl = 0;
                int j = blockIdx.x - 1;
                while (true) {
                    unsigned long long vv;
                    do { vv = state[j]; } while ((vv & 3ull) == 0ull);
                    excl += (int)(vv >> 2);
                    if ((vv & 3ull) == 2ull) break;
                    j--;
                }
                __threadfence();
                state[blockIdx.x] = ((unsigned long long)(excl + blockTotal) << 2) | 2ull;
                blockOffSh = excl;
            }
        }
    }
    __syncthreads();
    int run = blockOffSh + warpTot[wid] + (inc - s);
#pragma unroll
    for (int i = 0; i < 8; i++) {
        int idx = tbase + i;
        if (idx < n) {
            rowptr[idx] = run;
            fill[idx] = run;
            run += v[i];
        }
    }
}

__global__ void k_place(const int* __restrict__ src, const int* __restrict__ dst,
                        const float* __restrict__ w, const float* __restrict__ dinv,
                        int* fill, int2* csr, int e) {
    pdl_wait();   // k_scan's fill/dinv must be complete
    int i = blockIdx.x * blockDim.x + threadIdx.x;
    if (i < e) {
        int s = src[i], d = dst[i];
        float nm = dinv[s] * w[i] * dinv[d];
        int pos = atomicAdd(fill + d, 1);
        csr[pos] = make_int2(s, __float_as_int(nm));
    }
}

// ---------------- tf32 helpers ------------------------------------------------
__device__ __forceinline__ uint32_t f2tf32(float f) {
    uint32_t r;
    asm("cvt.rna.tf32.f32 %0, %1;" : "=r"(r) : "f"(f));
    return r;
}

__device__ __forceinline__ void mma_tf32(float c[4], uint32_t a0, uint32_t a1,
                                         uint32_t a2, uint32_t a3,
                                         uint32_t b0, uint32_t b1) {
    asm volatile(
        "mma.sync.aligned.m16n8k8.row.col.f32.tf32.tf32.f32 "
        "{%0,%1,%2,%3}, {%4,%5,%6,%7}, {%8,%9}, {%0,%1,%2,%3};"
        : "+f"(c[0]), "+f"(c[1]), "+f"(c[2]), "+f"(c[3])
        : "r"(a0), "r"(a1), "r"(a2), "r"(a3), "r"(b0), "r"(b1));
}

// ---------------- tf32 tensor-core GEMM with inline BN(+ReLU) on A ------------
// PDL: B staging (weights, independent) runs pre-wait; stats/A post-wait;
// launch_dependents after A is fully staged (all reads of A done).
template <int K, int NOUT, bool BN>
__global__ void k_gemm_tc(const float* __restrict__ A, const float* __restrict__ B,
                          float* __restrict__ C, int M,
                          const float* __restrict__ gamma, const float* __restrict__ beta,
                          const float* __restrict__ stats, float invN) {
    constexpr int BM = 128;
    constexpr int SA = K + 4;
    constexpr int SB = NOUT + 8;
    constexpr int NT = NOUT / 8;

    extern __shared__ uint32_t sm[];
    uint32_t* As = sm;              // [BM][SA]
    uint32_t* Bs = sm + BM * SA;    // [K][SB]
    __shared__ float sscale[K > 0 ? K : 1];
    __shared__ float sshift[K > 0 ? K : 1];

    const int tid = threadIdx.x;
    const int lane = tid & 31;
    const int warp = tid >> 5;
    const int rowBase = blockIdx.x * BM;

    // --- pre-wait prologue: stage B (weights are harness inputs) ---
    for (int l = tid; l < K * NOUT / 4; l += 256) {
        int r = l / (NOUT / 4);
        int c4 = l % (NOUT / 4);
        float4 v = *reinterpret_cast<const float4*>(B + (size_t)r * NOUT + c4 * 4);
        uint32_t* p = Bs + r * SB + c4 * 4;
        p[0] = f2tf32(v.x); p[1] = f2tf32(v.y); p[2] = f2tf32(v.z); p[3] = f2tf32(v.w);
    }

    pdl_wait();   // predecessor (agg) output now visible

    if (BN && tid < K) {
        float s = stats[tid];
        float q = stats[K + tid];
        float mean = s * invN;
        float var = q * invN - mean * mean;
        float sc = gamma[tid] * rsqrtf(var + EPS);
        sscale[tid] = sc;
        sshift[tid] = beta[tid] - mean * sc;
    }
    if (BN) __syncthreads();   // sscale/sshift visible before A staging

    for (int l = tid; l < BM * K / 4; l += 256) {
        int r = l / (K / 4);
        int c4 = l % (K / 4);
        int gr = rowBase + r;
        float4 v = make_float4(0.f, 0.f, 0.f, 0.f);
        if (gr < M) v = *reinterpret_cast<const float4*>(A + (size_t)gr * K + c4 * 4);
        if (BN) {
            v.x = fmaxf(fmaf(v.x, sscale[c4 * 4 + 0], sshift[c4 * 4 + 0]), 0.f);
            v.y = fmaxf(fmaf(v.y, sscale[c4 * 4 + 1], sshift[c4 * 4 + 1]), 0.f);
            v.z = fmaxf(fmaf(v.z, sscale[c4 * 4 + 2], sshift[c4 * 4 + 2]), 0.f);
            v.w = fmaxf(fmaf(v.w, sscale[c4 * 4 + 3], sshift[c4 * 4 + 3]), 0.f);
        }
        uint32_t* p = As + r * SA + c4 * 4;
        p[0] = f2tf32(v.x); p[1] = f2tf32(v.y); p[2] = f2tf32(v.z); p[3] = f2tf32(v.w);
    }
    __syncthreads();
    pdl_trigger();   // all global reads of A done; dependents may launch

    float acc[NT][4];
#pragma unroll
    for (int nt = 0; nt < NT; nt++) {
        acc[nt][0] = 0.f; acc[nt][1] = 0.f; acc[nt][2] = 0.f; acc[nt][3] = 0.f;
    }

    const int r0 = (warp << 4) + (lane >> 2);
    const int c0 = lane & 3;
    const int bcol = lane >> 2;

#pragma unroll 4
    for (int kk = 0; kk < K; kk += 8) {
        uint32_t a0 = As[r0 * SA + kk + c0];
        uint32_t a1 = As[(r0 + 8) * SA + kk + c0];
        uint32_t a2 = As[r0 * SA + kk + c0 + 4];
        uint32_t a3 = As[(r0 + 8) * SA + kk + c0 + 4];
#pragma unroll
        for (int nt = 0; nt < NT; nt++) {
            uint32_t b0 = Bs[(kk + c0) * SB + nt * 8 + bcol];
            uint32_t b1 = Bs[(kk + c0 + 4) * SB + nt * 8 + bcol];
            mma_tf32(acc[nt], a0, a1, a2, a3, b0, b1);
        }
    }

    int gr0 = rowBase + r0;
    int gr1 = gr0 + 8;
    if (gr0 < M) {
#pragma unroll
        for (int nt = 0; nt < NT; nt++)
            *reinterpret_cast<float2*>(C + (size_t)gr0 * NOUT + nt * 8 + c0 * 2) =
                make_float2(acc[nt][0], acc[nt][1]);
    }
    if (gr1 < M) {
#pragma unroll
        for (int nt = 0; nt < NT; nt++)
            *reinterpret_cast<float2*>(C + (size_t)gr1 * NOUT + nt * 8 + c0 * 2) =
                make_float2(acc[nt][2], acc[nt][3]);
    }
}

// ---------------- pull aggregation (8-edge unroll, 4 accumulator sets) --------
// PDL: trigger immediately (dependent gemm's pre-wait work touches only weights),
// then wait for predecessor gemm's h2.
template <int FEAT, bool STATS>
__global__ void k_agg(const int* __restrict__ rowptr, const int2* __restrict__ csr,
                      const float* __restrict__ h2, const float* __restrict__ bias,
                      const float* __restrict__ normself, float* __restrict__ out,
                      float* stats, int n) {
    constexpr int LPN = FEAT / 4;     // lanes per node
    constexpr int NPW = 32 / LPN;     // nodes per warp
    const int lane = threadIdx.x & 31;
    const int warpG = (blockIdx.x * blockDim.x + threadIdx.x) >> 5;
    const int nWarps = (gridDim.x * blockDim.x) >> 5;
    const int sub = lane / LPN;
    const int fc = lane % LPN;

    pdl_trigger();
    pdl_wait();

    float4 bb = *reinterpret_cast<const float4*>(bias + fc * 4);

    float s0 = 0.f, s1 = 0.f, s2 = 0.f, s3 = 0.f;
    float q0 = 0.f, q1 = 0.f, q2 = 0.f, q3 = 0.f;

    for (int node = warpG * NPW + sub; node < n; node += nWarps * NPW) {
        int beg = rowptr[node];
        int end = rowptr[node + 1];
        float ns = normself[node];
        float4 h = *reinterpret_cast<const float4*>(h2 + (size_t)node * FEAT + fc * 4);
        float4 aA = make_float4(fmaf(ns, h.x, bb.x), fmaf(ns, h.y, bb.y),
                                fmaf(ns, h.z, bb.z), fmaf(ns, h.w, bb.w));
        float4 aB = make_float4(0.f, 0.f, 0.f, 0.f);
        float4 aC = make_float4(0.f, 0.f, 0.f, 0.f);
        float4 aD = make_float4(0.f, 0.f, 0.f, 0.f);
        int e = beg;
        for (; e + 7 < end; e += 8) {
            int2 m0 = csr[e],     m1 = csr[e + 1], m2 = csr[e + 2], m3 = csr[e + 3];
            int2 m4 = csr[e + 4], m5 = csr[e + 5], m6 = csr[e + 6], m7 = csr[e + 7];
            float4 v0 = *reinterpret_cast<const float4*>(h2 + (size_t)m0.x * FEAT + fc * 4);
            float4 v1 = *reinterpret_cast<const float4*>(h2 + (size_t)m1.x * FEAT + fc * 4);
            float4 v2 = *reinterpret_cast<const float4*>(h2 + (size_t)m2.x * FEAT + fc * 4);
            float4 v3 = *reinterpret_cast<const float4*>(h2 + (size_t)m3.x * FEAT + fc * 4);
            float4 v4 = *reinterpret_cast<const float4*>(h2 + (size_t)m4.x * FEAT + fc * 4);
            float4 v5 = *reinterpret_cast<const float4*>(h2 + (size_t)m5.x * FEAT + fc * 4);
            float4 v6 = *reinterpret_cast<const float4*>(h2 + (size_t)m6.x * FEAT + fc * 4);
            float4 v7 = *reinterpret_cast<const float4*>(h2 + (size_t)m7.x * FEAT + fc * 4);
            float n0 = __int_as_float(m0.y), n1 = __int_as_float(m1.y);
            float n2 = __int_as_float(m2.y), n3 = __int_as_float(m3.y);
            float n4 = __int_as_float(m4.y), n5 = __int_as_float(m5.y);
            float n6 = __int_as_float(m6.y), n7 = __int_as_float(m7.y);
            aA.x = fmaf(n0, v0.x, aA.x); aB.x = fmaf(n1, v1.x, aB.x);
            aC.x = fmaf(n2, v2.x, aC.x); aD.x = fmaf(n3, v3.x, aD.x);
            aA.y = fmaf(n0, v0.y, aA.y); aB.y = fmaf(n1, v1.y, aB.y);
            aC.y = fmaf(n2, v2.y, aC.y); aD.y = fmaf(n3, v3.y, aD.y);
            aA.z = fmaf(n0, v0.z, aA.z); aB.z = fmaf(n1, v1.z, aB.z);
            aC.z = fmaf(n2, v2.z, aC.z); aD.z = fmaf(n3, v3.z, aD.z);
            aA.w = fmaf(n0, v0.w, aA.w); aB.w = fmaf(n1, v1.w, aB.w);
            aC.w = fmaf(n2, v2.w, aC.w); aD.w = fmaf(n3, v3.w, aD.w);
            aA.x = fmaf(n4, v4.x, aA.x); aB.x = fmaf(n5, v5.x, aB.x);
            aC.x = fmaf(n6, v6.x, aC.x); aD.x = fmaf(n7, v7.x, aD.x);
            aA.y = fmaf(n4, v4.y, aA.y); aB.y = fmaf(n5, v5.y, aB.y);
            aC.y = fmaf(n6, v6.y, aC.y); aD.y = fmaf(n7, v7.y, aD.y);
            aA.z = fmaf(n4, v4.z, aA.z); aB.z = fmaf(n5, v5.z, aB.z);
            aC.z = fmaf(n6, v6.z, aC.z); aD.z = fmaf(n7, v7.z, aD.z);
            aA.w = fmaf(n4, v4.w, aA.w); aB.w = fmaf(n5, v5.w, aB.w);
            aC.w = fmaf(n6, v6.w, aC.w); aD.w = fmaf(n7, v7.w, aD.w);
        }
        for (; e + 1 < end; e += 2) {
            int2 m0 = csr[e], m1 = csr[e + 1];
            float4 v0 = *reinterpret_cast<const float4*>(h2 + (size_t)m0.x * FEAT + fc * 4);
            float4 v1 = *reinterpret_cast<const float4*>(h2 + (size_t)m1.x * FEAT + fc * 4);
            float n0 = __int_as_float(m0.y), n1 = __int_as_float(m1.y);
            aA.x = fmaf(n0, v0.x, aA.x); aB.x = fmaf(n1, v1.x, aB.x);
            aA.y = fmaf(n0, v0.y, aA.y); aB.y = fmaf(n1, v1.y, aB.y);
            aA.z = fmaf(n0, v0.z, aA.z); aB.z = fmaf(n1, v1.z, aB.z);
            aA.w = fmaf(n0, v0.w, aA.w); aB.w = fmaf(n1, v1.w, aB.w);
        }
        if (e < end) {
            int2 m0 = csr[e];
            float4 v0 = *reinterpret_cast<const float4*>(h2 + (size_t)m0.x * FEAT + fc * 4);
            float n0 = __int_as_float(m0.y);
            aA.x = fmaf(n0, v0.x, aA.x);
            aA.y = fmaf(n0, v0.y, aA.y);
            aA.z = fmaf(n0, v0.z, aA.z);
            aA.w = fmaf(n0, v0.w, aA.w);
        }
        float4 acc = make_float4((aA.x + aB.x) + (aC.x + aD.x),
                                 (aA.y + aB.y) + (aC.y + aD.y),
                                 (aA.z + aB.z) + (aC.z + aD.z),
                                 (aA.w + aB.w) + (aC.w + aD.w));
        *reinterpret_cast<float4*>(out + (size_t)node * FEAT + fc * 4) = acc;
        if (STATS) {
            s0 += acc.x; s1 += acc.y; s2 += acc.z; s3 += acc.w;
            q0 = fmaf(acc.x, acc.x, q0); q1 = fmaf(acc.y, acc.y, q1);
            q2 = fmaf(acc.z, acc.z, q2); q3 = fmaf(acc.w, acc.w, q3);
        }
    }

    if (STATS) {
#pragma unroll
        for (int off = 16; off >= LPN; off >>= 1) {
            s0 += __shfl_down_sync(0xffffffffu, s0, off);
            s1 += __shfl_down_sync(0xffffffffu, s1, off);
            s2 += __shfl_down_sync(0xffffffffu, s2, off);
            s3 += __shfl_down_sync(0xffffffffu, s3, off);
            q0 += __shfl_down_sync(0xffffffffu, q0, off);
            q1 += __shfl_down_sync(0xffffffffu, q1, off);
            q2 += __shfl_down_sync(0xffffffffu, q2, off);
            q3 += __shfl_down_sync(0xffffffffu, q3, off);
        }
        __shared__ float sh_s[8][FEAT];
        __shared__ float sh_q[8][FEAT];
        const int wid = threadIdx.x >> 5;
        if (lane < LPN) {
            sh_s[wid][fc * 4 + 0] = s0; sh_s[wid][fc * 4 + 1] = s1;
            sh_s[wid][fc * 4 + 2] = s2; sh_s[wid][fc * 4 + 3] = s3;
            sh_q[wid][fc * 4 + 0] = q0; sh_q[wid][fc * 4 + 1] = q1;
            sh_q[wid][fc * 4 + 2] = q2; sh_q[wid][fc * 4 + 3] = q3;
        }
        __syncthreads();
        int tid = threadIdx.x;
        if (tid < FEAT) {
            float a = 0.f, b = 0.f;
#pragma unroll
            for (int w = 0; w < 8; w++) { a += sh_s[w][tid]; b += sh_q[w][tid]; }
            atomicAdd(&stats[tid], a);
            atomicAdd(&stats[FEAT + tid], b);
        }
    }
}

// ---------------- host orchestration -----------------------------------------
static inline int cdiv(int a, int b) { return (a + b - 1) / b; }

extern "C" void kernel_launch(void* const* d_in, const int* in_sizes, int n_in,
                              void* d_out, int out_size) {
    const float* x      = (const float*)d_in[0];
    const int*   src    = (const int*)d_in[1];
    const int*   dst    = (const int*)d_in[2];
    const float* weight = (const float*)d_in[3];
    const float* W1 = (const float*)d_in[4];
    const float* b1 = (const float*)d_in[5];
    const float* ga1 = (const float*)d_in[6];
    const float* be1 = (const float*)d_in[7];
    const float* W2 = (const float*)d_in[8];
    const float* b2 = (const float*)d_in[9];
    const float* ga2 = (const float*)d_in[10];
    const float* be2 = (const float*)d_in[11];
    const float* W3 = (const float*)d_in[12];
    const float* b3 = (const float*)d_in[13];

    const int N = in_sizes[0] / 128;
    const int E = in_sizes[1];
    float* outp = (float*)d_out;

    void *p_deg, *p_cnt, *p_fill, *p_rowptr, *p_csr, *p_dinv, *p_ns, *p_h2, *p_out;
    void *p_state, *p_stats;
    cudaGetSymbolAddress(&p_deg, g_deg);
    cudaGetSymbolAddress(&p_cnt, g_cnt);
    cudaGetSymbolAddress(&p_fill, g_fill);
    cudaGetSymbolAddress(&p_rowptr, g_rowptr);
    cudaGetSymbolAddress(&p_csr, g_csr);
    cudaGetSymbolAddress(&p_dinv, g_dinv);
    cudaGetSymbolAddress(&p_ns, g_normself);
    cudaGetSymbolAddress(&p_h2, g_h2);
    cudaGetSymbolAddress(&p_out, g_out);
    cudaGetSymbolAddress(&p_state, g_scanstate);
    cudaGetSymbolAddress(&p_stats, g_stats);
    float* deg = (float*)p_deg;
    int* cnt = (int*)p_cnt;
    int* fill = (int*)p_fill;
    int* rowptr = (int*)p_rowptr;
    int2* csr = (int2*)p_csr;
    float* dinv = (float*)p_dinv;
    float* normself = (float*)p_ns;
    float* h2 = (float*)p_h2;
    float* agg = (float*)p_out;
    unsigned long long* scanstate = (unsigned long long*)p_state;
    float* stats1 = (float*)p_stats;        // layer1: 256 floats
    float* stats2 = (float*)p_stats + 256;  // layer2: 128 floats

    const float invN = 1.0f / (float)N;

    const int smem1 = (128 * (128 + 4) + 128 * (128 + 8)) * 4;
    const int smem2 = (128 * (128 + 4) + 128 * (64 + 8)) * 4;
    const int smem3 = (128 * (64 + 4) + 64 * (32 + 8)) * 4;
    cudaFuncSetAttribute(k_gemm_tc<128, 128, false>,
                         cudaFuncAttributeMaxDynamicSharedMemorySize, smem1);
    cudaFuncSetAttribute(k_gemm_tc<128, 64, true>,
                         cudaFuncAttributeMaxDynamicSharedMemorySize, smem2);
    cudaFuncSetAttribute(k_gemm_tc<64, 32, true>,
                         cudaFuncAttributeMaxDynamicSharedMemorySize, smem3);

    // side stream + fork/join events (host-side objects only)
    cudaStream_t s2;
    cudaEvent_t evFork, evJoin;
    cudaStreamCreateWithFlags(&s2, cudaStreamNonBlocking);
    cudaEventCreateWithFlags(&evFork, cudaEventDisableTiming);
    cudaEventCreateWithFlags(&evJoin, cudaEventDisableTiming);

    const int scanGrid = cdiv(N, 2048);   // 25 blocks for N=50000
    const int gemmGrid = cdiv(N, 128);
    const int aggGrid = 1184;             // 8 blocks/SM

    // PDL launch attribute (shared)
    cudaLaunchAttribute pdlAttr[1];
    pdlAttr[0].id = cudaLaunchAttributeProgrammaticStreamSerialization;
    pdlAttr[0].val.programmaticStreamSerializationAllowed = 1;

    // ---- fork: CSR/normalization prep on s2, concurrent with Layer-1 GEMM ----
    cudaEventRecord(evFork, 0);
    cudaStreamWaitEvent(s2, evFork, 0);

    k_init<<<cdiv(N, 256), 256, 0, s2>>>(deg, cnt, stats1, scanstate, N);
    {   // prep_edge: PDL after init (launch setup hides under init)
        cudaLaunchConfig_t cfg{};
        cfg.gridDim = dim3(cdiv(E, 256), 1, 1);
        cfg.blockDim = dim3(256, 1, 1);
        cfg.stream = s2;
        cfg.attrs = pdlAttr; cfg.numAttrs = 1;
        cudaLaunchKernelEx(&cfg, k_prep_edge, dst, weight, deg, cnt, E);
    }
    {   // scan: PDL after prep_edge
        cudaLaunchConfig_t cfg{};
        cfg.gridDim = dim3(scanGrid, 1, 1);
        cfg.blockDim = dim3(256, 1, 1);
        cfg.stream = s2;
        cfg.attrs = pdlAttr; cfg.numAttrs = 1;
        cudaLaunchKernelEx(&cfg, k_scan, (const int*)cnt, (const float*)deg,
                           dinv, normself, rowptr, fill,
                           (volatile unsigned long long*)scanstate, N, E);
    }
    {   // place: PDL after scan
        cudaLaunchConfig_t cfg{};
        cfg.gridDim = dim3(cdiv(E, 256), 1, 1);
        cfg.blockDim = dim3(256, 1, 1);
        cfg.stream = s2;
        cfg.attrs = pdlAttr; cfg.numAttrs = 1;
        cudaLaunchKernelEx(&cfg, k_place, src, dst, weight, (const float*)dinv,
                           fill, csr, E);
    }
    cudaEventRecord(evJoin, s2);

    // Layer-1 GEMM on main stream (independent of prep; starts at t=0)
    k_gemm_tc<128, 128, false><<<gemmGrid, 256, smem1>>>(x, W1, h2, N,
                                                         nullptr, nullptr, nullptr, invN);

    // ---- join: everything after needs both GEMM1 and the CSR ----
    cudaStreamWaitEvent(0, evJoin, 0);

    // agg1: plain launch (predecessor is an event-wait, not a kernel)
    k_agg<128, true><<<aggGrid, 256>>>(rowptr, csr, h2, b1, normself, agg, stats1, N);

    {
        cudaLaunchConfig_t cfg{};
        cfg.gridDim = dim3(gemmGrid, 1, 1);
        cfg.blockDim = dim3(256, 1, 1);
        cfg.dynamicSmemBytes = smem2;
        cfg.stream = 0;
        cfg.attrs = pdlAttr;
        cfg.numAttrs = 1;
        cudaLaunchKernelEx(&cfg, k_gemm_tc<128, 64, true>, (const float*)agg, W2, h2, N,
                           ga1, be1, (const float*)stats1, invN);
    }
    {
        cudaLaunchConfig_t cfg{};
        cfg.gridDim = dim3(aggGrid, 1, 1);
        cfg.blockDim = dim3(256, 1, 1);
        cfg.dynamicSmemBytes = 0;
        cfg.stream = 0;
        cfg.attrs = pdlAttr;
        cfg.numAttrs = 1;
        cudaLaunchKernelEx(&cfg, k_agg<64, true>, (const int*)rowptr, (const int2*)csr,
                           (const float*)h2, b2, (const float*)normself, agg, stats2, N);
    }
    {
        cudaLaunchConfig_t cfg{};
        cfg.gridDim = dim3(gemmGrid, 1, 1);
        cfg.blockDim = dim3(256, 1, 1);
        cfg.dynamicSmemBytes = smem3;
        cfg.stream = 0;
        cfg.attrs = pdlAttr;
        cfg.numAttrs = 1;
        cudaLaunchKernelEx(&cfg, k_gemm_tc<64, 32, true>, (const float*)agg, W3, h2, N,
                           ga2, be2, (const float*)stats2, invN);
    }
    {
        cudaLaunchConfig_t cfg{};
        cfg.gridDim = dim3(aggGrid, 1, 1);
        cfg.blockDim = dim3(256, 1, 1);
        cfg.dynamicSmemBytes = 0;
        cfg.stream = 0;
        cfg.attrs = pdlAttr;
        cfg.numAttrs = 1;
        cudaLaunchKernelEx(&cfg, k_agg<32, false>, (const int*)rowptr, (const int2*)csr,
                           (const float*)h2, b3, (const float*)normself, outp,
                           (float*)nullptr, N);
    }
}